// round 12
// baseline (speedup 1.0000x reference)
#include <cuda_runtime.h>
#include <cstdint>

// QuantumLSTM: B=2048, T=64, IN=8, HID=6 qubits, OUT=8, NLAYERS=2.
//
// X-basis pure-phase formulation (see prior rounds):
//   beta^{(g)}_k = a_{sigma^2(k)} + C^{(g)}_k,
//   <Z_w> = (1/64) sum_k cos(beta_{k xor e_w} - beta_k)  (pair-dedup, weight 2).
// GATE-SPLIT: 2 warps per sample. Warp 0 owns gates {f,i}, warp 1 owns {g,o}.
// Per-gate work (cos, q, reduce) halves per warp; the four activations are
// exchanged once per step via a double-buffered smem slab with a single
// __syncthreads(). 4096 warps total -> ~2x occupancy vs one-warp-per-sample.

namespace {
constexpr int BATCH = 2048;
constexpr int TSTEPS = 64;
constexpr float TWO_PI = 6.28318530717958647692f;
}

__device__ __forceinline__ float shx(float v, int m) {
    return __shfl_xor_sync(0xffffffffu, v, m);
}
__device__ __forceinline__ float shi(float v, int src) {
    return __shfl_sync(0xffffffffu, v, src);
}
__device__ __forceinline__ float tanh_fast(float x) {
    float r;
    asm("tanh.approx.f32 %0, %1;" : "=f"(r) : "f"(x));
    return r;
}
__device__ __forceinline__ float reduce2pi(float a) {
    return a - TWO_PI * rintf(a * (1.0f / TWO_PI));
}

// X-basis CNOT ring composed permutation: state'[k] = state[sigma(k)].
__device__ __forceinline__ int ring_src_x(int k) {
    int j = k;
    j ^= (j >> 5) & 1;
    j ^= (j & 1) << 1;
    j ^= ((j >> 1) & 1) << 2;
    j ^= ((j >> 2) & 1) << 3;
    j ^= ((j >> 3) & 1) << 4;
    j ^= ((j >> 4) & 1) << 5;
    return j;
}

__device__ __forceinline__ float phaseA(const float* w6, int j) {
    float s = 0.0f;
#pragma unroll
    for (int w = 0; w < 6; w++)
        s += (((j >> (5 - w)) & 1) ? 0.5f : -0.5f) * w6[w];
    return s;
}

// C^{(g)}(j) = A1(sigma^2 j) + A2(sigma j)
__device__ __forceinline__ float Cphase(const float* wp, int j) {
    int s1 = ring_src_x(j);
    return phaseA(wp, ring_src_x(s1)) + phaseA(wp + 6, s1);
}

__global__ void __launch_bounds__(64, 12) qlstm_kernel(
    const float* __restrict__ x,      // [B, T, 8]
    const float* __restrict__ W_in,   // [6, 16]
    const float* __restrict__ b_in,   // [6]
    const float* __restrict__ W_out,  // [8, 6]
    const float* __restrict__ b_out,  // [8]
    const float* __restrict__ wf,     // [2, 6]
    const float* __restrict__ wi,
    const float* __restrict__ wg,
    const float* __restrict__ wo,
    float* __restrict__ out)          // [B, T, 8]
{
    const int tid = threadIdx.x;
    const int lane = tid & 31;
    const int warp = tid >> 5;        // 0: gates {f,i}, 1: gates {g,o}
    const int s = blockIdx.x;

    __shared__ float4 actbuf[2][8];   // [buffer][channel] -> (f, i, g, o)

    const int kLo = lane;
    const int kHi = lane + 32;
    const int gb = (lane >> 4) & 1;   // gate bit within this warp's pair
    const int ch = lane & 7;          // lane's LSTM channel

    // ---- embedding sign vectors for aperm = a(sigma^2(k)) ----
    const int s2Lo = ring_src_x(ring_src_x(kLo));
    const int s2Hi = ring_src_x(ring_src_x(kHi));
    float sgnP[6], sgnH[6];
#pragma unroll
    for (int w = 0; w < 6; w++) {
        sgnP[w] = ((s2Lo >> (5 - w)) & 1) ? 0.5f : -0.5f;
        sgnH[w] = ((s2Hi >> (5 - w)) & 1) ? 0.5f : -0.5f;
    }

    // ---- fold sign vectors through W_in: apl = WP.[h;x] + bP ----
    float WP[16], WH[16];
    float bP = 0.0f, bH = 0.0f;
#pragma unroll
    for (int j = 0; j < 16; j++) { WP[j] = 0.0f; WH[j] = 0.0f; }
#pragma unroll
    for (int w = 0; w < 6; w++) {
        float bw = b_in[w];
        bP = fmaf(sgnP[w], bw, bP);
        bH = fmaf(sgnH[w], bw, bH);
#pragma unroll
        for (int j = 0; j < 16; j++) {
            float wv = W_in[w * 16 + j];
            WP[j] = fmaf(sgnP[w], wv, WP[j]);
            WH[j] = fmaf(sgnH[w], wv, WH[j]);
        }
    }

    // ---- per-gate constants for THIS warp's two gates, gate-permuted by gb:
    // slot jg holds constants for gate g = 2*warp + (jg ^ gb).
    float dc0P[2], dcSP[2][5];
#pragma unroll
    for (int jg = 0; jg < 2; jg++) {
        int g = 2 * warp + (jg ^ gb);
        const float* wp = (g == 0) ? wf : (g == 1) ? wi : (g == 2) ? wg : wo;
        float cLo = Cphase(wp, kLo);
        float cHi = Cphase(wp, kHi);
        dc0P[jg] = reduce2pi(cHi - cLo);
#pragma unroll
        for (int i = 0; i < 5; i++) {
            int m = 16 >> i;
            int kSel = (lane & m) ? kHi : kLo;
            float cS = (lane & m) ? cHi : cLo;
            dcSP[jg][i] = reduce2pi(Cphase(wp, kSel ^ m) - cS);
        }
    }

    // ---- W_out row: weight 2 per wire (pair-dedup) ----
    float woutS[6];
#pragma unroll
    for (int w = 0; w < 6; w++)
        woutS[w] = W_out[ch * 6 + w] * (2.0f / 64.0f);
    const float boutv = b_out[ch];

    // ---- activation constants: my gate index = 2*warp + gb; gate 2 = tanh ----
    const bool isTanh = (warp == 1) && (gb == 0);
    const float sT = isTanh ? 1.0f : 0.5f;
    const float aT = isTanh ? 1.0f : 0.5f;
    const float bT = isTanh ? 0.0f : 0.5f;

    const float4* xrow = (const float4*)(x + (size_t)s * TSTEPS * 8);
    float* orow = out + (size_t)s * TSTEPS * 8;

    float creg = 0.0f, hreg = 0.0f;  // lane owns channel ch (replicated)

    for (int t = 0; t < TSTEPS; t++) {
        // ---- x-chain (independent of h) ----
        float4 xa = xrow[t * 2];
        float4 xb = xrow[t * 2 + 1];
        float xpl = bP, xph = bH;
        {
            float xs[8] = {xa.x, xa.y, xa.z, xa.w, xb.x, xb.y, xb.z, xb.w};
#pragma unroll
            for (int j = 0; j < 8; j++) {
                xpl = fmaf(WP[8 + j], xs[j], xpl);
                xph = fmaf(WH[8 + j], xs[j], xph);
            }
        }

        // ---- h-chain (recurrence-critical) ----
        float hpl = 0.0f, hph = 0.0f;
#pragma unroll
        for (int j = 0; j < 8; j++) {
            float hj = shi(hreg, j);
            hpl = fmaf(WP[j], hj, hpl);
            hph = fmaf(WH[j], hj, hph);
        }
        float apl = reduce2pi(xpl + hpl);
        float aph = reduce2pi(xph + hph);

        // ---- one shuffle per wire serves both pair orientations ----
        float Da0 = aph - apl;
        float DaS[5];
#pragma unroll
        for (int i = 0; i < 5; i++) {
            const int m = 16 >> i;
            const bool b = (lane & m) != 0;
            float send = b ? apl : aph;   // partner needs my OPPOSITE slot
            float own  = b ? aph : apl;
            DaS[i] = shx(send, m) - own;
        }

        // ---- partials for this warp's 2 gates: q[jg*6 + w] ----
        float q[12];
#pragma unroll
        for (int jg = 0; jg < 2; jg++) {
            q[jg * 6] = __cosf(Da0 + dc0P[jg]);
#pragma unroll
            for (int i = 0; i < 5; i++)
                q[jg * 6 + 1 + i] = __cosf(DaS[i] + dcSP[jg][i]);
        }

        // ---- gate stage (mask 16): selection-free xor-permuted fold ----
#pragma unroll
        for (int i = 0; i < 6; i++)
            q[i] += shx(q[i + 6], 16);

        // ---- routed stages masks 8,4,2 (slot bits -> lane bits 3,2,1) ----
        float qq[8] = {q[0], q[1], q[2], q[3], q[4], q[5], 0.0f, 0.0f};
#pragma unroll
        for (int st = 0; st < 3; st++) {
            const int m = 8 >> st;       // 8, 4, 2
            const int half = 4 >> st;    // 4, 2, 1
            const bool up = (lane & m) != 0;
#pragma unroll
            for (int i = 0; i < 4; i++) {
                if (i < half) {
                    float keep = up ? qq[i + half] : qq[i];
                    float send = up ? qq[i] : qq[i + half];
                    qq[i] = keep + shx(send, m);
                }
            }
        }
        // ---- final fold over mask 1 ----
        float S = qq[0] + shx(qq[0], 1);
        // lane l holds e[g][w] with g = 2*warp + bit4(l), w = (l>>1)&7.

        // ---- z for (g = 2*warp + bit4, ch = lane&7) via shuffle-matmul ----
        float z = boutv;
#pragma unroll
        for (int w = 0; w < 6; w++)
            z = fmaf(woutS[w], shi(S, (lane & 16) | (w << 1)), z);

        // ---- one activation per lane ----
        float act = fmaf(aT, tanh_fast(sT * z), bT);

        // ---- exchange the 4 gate activations via smem (double-buffered) ----
        if ((lane & 8) == 0)
            ((float*)&actbuf[t & 1][ch])[2 * warp + gb] = act;
        __syncthreads();
        float4 a4 = actbuf[t & 1][ch];

        // ---- LSTM cell (identical in both warps; h needed by both) ----
        creg = fmaf(a4.x, creg, a4.y * a4.z);
        hreg = a4.w * tanh_fast(creg);
        // predicated store: only warp 0, lanes 0..7 emit the output row
        if (warp == 0 && lane < 8) orow[t * 8 + lane] = hreg;
    }
}

extern "C" void kernel_launch(void* const* d_in, const int* in_sizes, int n_in,
                              void* d_out, int out_size) {
    const float* x     = (const float*)d_in[0];
    const float* W_in  = (const float*)d_in[1];
    const float* b_in  = (const float*)d_in[2];
    const float* W_out = (const float*)d_in[3];
    const float* b_out = (const float*)d_in[4];
    const float* wf    = (const float*)d_in[5];
    const float* wi    = (const float*)d_in[6];
    const float* wg    = (const float*)d_in[7];
    const float* wo    = (const float*)d_in[8];
    float* out = (float*)d_out;

    qlstm_kernel<<<BATCH, 64>>>(x, W_in, b_in, W_out, b_out, wf, wi, wg, wo, out);
}

// round 13
// speedup vs baseline: 1.5018x; 1.5018x over previous
#include <cuda_runtime.h>
#include <cstdint>

// QuantumLSTM: B=2048, T=64, IN=8, HID=6 qubits, OUT=8, NLAYERS=2.
//
// X-basis pure-phase formulation:
//   beta^{(g)}_k = a_{sigma^2(k)} + C^{(g)}_k,
//   <Z_w> = (1/64) sum_k cos(beta_{k xor e_w} - beta_k)  (pair-dedup, weight 2).
// Round 13: ILP-2 — one warp processes TWO independent samples (s, s+1024)
// with interleaved register streams. Constants shared; no barriers; chip-total
// instruction count unchanged vs R9. 1024 warps x ILP2.

namespace {
constexpr int BATCH = 2048;
constexpr int TSTEPS = 64;
constexpr int HALF = BATCH / 2;
constexpr float TWO_PI = 6.28318530717958647692f;
}

__device__ __forceinline__ float shx(float v, int m) {
    return __shfl_xor_sync(0xffffffffu, v, m);
}
__device__ __forceinline__ float shi(float v, int src) {
    return __shfl_sync(0xffffffffu, v, src);
}
__device__ __forceinline__ float tanh_fast(float x) {
    float r;
    asm("tanh.approx.f32 %0, %1;" : "=f"(r) : "f"(x));
    return r;
}
__device__ __forceinline__ float reduce2pi(float a) {
    return a - TWO_PI * rintf(a * (1.0f / TWO_PI));
}

// X-basis CNOT ring composed permutation: state'[k] = state[sigma(k)].
__device__ __forceinline__ int ring_src_x(int k) {
    int j = k;
    j ^= (j >> 5) & 1;
    j ^= (j & 1) << 1;
    j ^= ((j >> 1) & 1) << 2;
    j ^= ((j >> 2) & 1) << 3;
    j ^= ((j >> 3) & 1) << 4;
    j ^= ((j >> 4) & 1) << 5;
    return j;
}

__device__ __forceinline__ float phaseA(const float* w6, int j) {
    float s = 0.0f;
#pragma unroll
    for (int w = 0; w < 6; w++)
        s += (((j >> (5 - w)) & 1) ? 0.5f : -0.5f) * w6[w];
    return s;
}

// C^{(g)}(j) = A1(sigma^2 j) + A2(sigma j)
__device__ __forceinline__ float Cphase(const float* wp, int j) {
    int s1 = ring_src_x(j);
    return phaseA(wp, ring_src_x(s1)) + phaseA(wp + 6, s1);
}

__global__ void __launch_bounds__(32, 4) qlstm_kernel(
    const float* __restrict__ x,      // [B, T, 8]
    const float* __restrict__ W_in,   // [6, 16]
    const float* __restrict__ b_in,   // [6]
    const float* __restrict__ W_out,  // [8, 6]
    const float* __restrict__ b_out,  // [8]
    const float* __restrict__ wf,     // [2, 6]
    const float* __restrict__ wi,
    const float* __restrict__ wg,
    const float* __restrict__ wo,
    float* __restrict__ out)          // [B, T, 8]
{
    const int lane = threadIdx.x;
    const int kLo = lane;
    const int kHi = lane + 32;
    const int lg = (lane >> 3) & 3;   // lane's gate-group bits
    const int ch = lane & 7;          // lane's LSTM channel

    // ---- embedding sign vectors for aperm = a(sigma^2(k)) ----
    const int s2Lo = ring_src_x(ring_src_x(kLo));
    const int s2Hi = ring_src_x(ring_src_x(kHi));
    float sgnP[6], sgnH[6];
#pragma unroll
    for (int w = 0; w < 6; w++) {
        sgnP[w] = ((s2Lo >> (5 - w)) & 1) ? 0.5f : -0.5f;
        sgnH[w] = ((s2Hi >> (5 - w)) & 1) ? 0.5f : -0.5f;
    }

    // ---- fold sign vectors through W_in: apl = WP.[h;x] + bP ----
    float WP[16], WH[16];
    float bP = 0.0f, bH = 0.0f;
#pragma unroll
    for (int j = 0; j < 16; j++) { WP[j] = 0.0f; WH[j] = 0.0f; }
#pragma unroll
    for (int w = 0; w < 6; w++) {
        float bw = b_in[w];
        bP = fmaf(sgnP[w], bw, bP);
        bH = fmaf(sgnH[w], bw, bH);
#pragma unroll
        for (int j = 0; j < 16; j++) {
            float wv = W_in[w * 16 + j];
            WP[j] = fmaf(sgnP[w], wv, WP[j]);
            WH[j] = fmaf(sgnH[w], wv, WH[j]);
        }
    }

    // ---- per-gate constants, PRE-PERMUTED by lane's gate bits:
    // slot jg holds constants for gate g = jg ^ lg.
    float dc0P[4], dcSP[4][5];
#pragma unroll
    for (int jg = 0; jg < 4; jg++) {
        int g = jg ^ lg;
        const float* wp = (g == 0) ? wf : (g == 1) ? wi : (g == 2) ? wg : wo;
        float cLo = Cphase(wp, kLo);
        float cHi = Cphase(wp, kHi);
        dc0P[jg] = reduce2pi(cHi - cLo);
#pragma unroll
        for (int i = 0; i < 5; i++) {
            int m = 16 >> i;
            int kSel = (lane & m) ? kHi : kLo;
            float cS = (lane & m) ? cHi : cLo;
            dcSP[jg][i] = reduce2pi(Cphase(wp, kSel ^ m) - cS);
        }
    }

    // ---- W_out row: weight 2 per wire (pair-dedup) ----
    float woutS[6];
#pragma unroll
    for (int w = 0; w < 6; w++)
        woutS[w] = W_out[ch * 6 + w] * (2.0f / 64.0f);
    const float boutv = b_out[ch];

    // ---- branch-free activation: act = aT * tanh(sT*z) + bT ----
    const float sT = (lg == 2) ? 1.0f : 0.5f;
    const float aT = (lg == 2) ? 1.0f : 0.5f;
    const float bT = (lg == 2) ? 0.0f : 0.5f;

    // ---- two independent samples per warp ----
    const int s0 = blockIdx.x;
    const int s1 = blockIdx.x + HALF;
    const float4* xr0 = (const float4*)(x + (size_t)s0 * TSTEPS * 8);
    const float4* xr1 = (const float4*)(x + (size_t)s1 * TSTEPS * 8);
    float* or0 = out + (size_t)s0 * TSTEPS * 8;
    float* or1 = out + (size_t)s1 * TSTEPS * 8;

    float creg[2] = {0.0f, 0.0f};
    float hreg[2] = {0.0f, 0.0f};

    for (int t = 0; t < TSTEPS; t++) {
        float apl[2], aph[2];

        // ---- x-chains (independent of h) ----
#pragma unroll
        for (int u = 0; u < 2; u++) {
            const float4* xr = u ? xr1 : xr0;
            float4 xa = xr[t * 2];
            float4 xb = xr[t * 2 + 1];
            float xpl = bP, xph = bH;
            float xs[8] = {xa.x, xa.y, xa.z, xa.w, xb.x, xb.y, xb.z, xb.w};
#pragma unroll
            for (int j = 0; j < 8; j++) {
                xpl = fmaf(WP[8 + j], xs[j], xpl);
                xph = fmaf(WH[8 + j], xs[j], xph);
            }
            apl[u] = xpl;
            aph[u] = xph;
        }

        // ---- h-chains ----
#pragma unroll
        for (int u = 0; u < 2; u++) {
            float hpl = 0.0f, hph = 0.0f;
#pragma unroll
            for (int j = 0; j < 8; j++) {
                float hj = shi(hreg[u], j);
                hpl = fmaf(WP[j], hj, hpl);
                hph = fmaf(WH[j], hj, hph);
            }
            apl[u] = reduce2pi(apl[u] + hpl);
            aph[u] = reduce2pi(aph[u] + hph);
        }

        // ---- one shuffle per wire serves both pair orientations ----
        float Da0[2], DaS[2][5];
#pragma unroll
        for (int i = 0; i < 5; i++) {
            const int m = 16 >> i;
            const bool b = (lane & m) != 0;
#pragma unroll
            for (int u = 0; u < 2; u++) {
                float send = b ? apl[u] : aph[u];
                float own  = b ? aph[u] : apl[u];
                DaS[u][i] = shx(send, m) - own;
            }
        }
#pragma unroll
        for (int u = 0; u < 2; u++) Da0[u] = aph[u] - apl[u];

        // ---- per-lane partials, dense gate-permuted slots: q[u][jg*6+w] ----
        float q[2][24];
#pragma unroll
        for (int jg = 0; jg < 4; jg++) {
#pragma unroll
            for (int u = 0; u < 2; u++)
                q[u][jg * 6] = __cosf(Da0[u] + dc0P[jg]);
#pragma unroll
            for (int i = 0; i < 5; i++) {
#pragma unroll
                for (int u = 0; u < 2; u++)
                    q[u][jg * 6 + 1 + i] = __cosf(DaS[u][i] + dcSP[jg][i]);
            }
        }

        // ---- gate stages: SELECTION-FREE (xor-permuted), dense layout ----
#pragma unroll
        for (int i = 0; i < 12; i++) {
#pragma unroll
            for (int u = 0; u < 2; u++)
                q[u][i] += shx(q[u][i + 12], 16);
        }
#pragma unroll
        for (int i = 0; i < 6; i++) {
#pragma unroll
            for (int u = 0; u < 2; u++)
                q[u][i] += shx(q[u][i + 6], 8);
        }

        // ---- w-stages (routed): masks 4, 2, 1 over 8 slots (2 zero pads) ----
        float qq[2][8];
#pragma unroll
        for (int u = 0; u < 2; u++) {
#pragma unroll
            for (int i = 0; i < 6; i++) qq[u][i] = q[u][i];
            qq[u][6] = 0.0f;
            qq[u][7] = 0.0f;
        }
#pragma unroll
        for (int half = 4; half >= 1; half >>= 1) {
            const bool up = (lane & half) != 0;
#pragma unroll
            for (int i = 0; i < half; i++) {
#pragma unroll
                for (int u = 0; u < 2; u++) {
                    float keep = up ? qq[u][i + half] : qq[u][i];
                    float send = up ? qq[u][i] : qq[u][i + half];
                    qq[u][i] = keep + shx(send, half);
                }
            }
        }
        // lane l holds S for (gate = l>>3, w = l&7); w=6,7 are zero pads.

        // ---- z via shuffle-matmul, activation, gather, cell ----
        const int base = lane & 24;
        float z[2] = {boutv, boutv};
#pragma unroll
        for (int w = 0; w < 6; w++) {
#pragma unroll
            for (int u = 0; u < 2; u++)
                z[u] = fmaf(woutS[w], shi(qq[u][0], base + w), z[u]);
        }

#pragma unroll
        for (int u = 0; u < 2; u++) {
            float act = fmaf(aT, tanh_fast(sT * z[u]), bT);
            float fg = shi(act, ch);
            float ig = shi(act, ch + 8);
            float gg = shi(act, ch + 16);
            float og = shi(act, ch + 24);
            creg[u] = fmaf(fg, creg[u], ig * gg);
            hreg[u] = og * tanh_fast(creg[u]);
        }
        if (lane < 8) {
            or0[t * 8 + lane] = hreg[0];
            or1[t * 8 + lane] = hreg[1];
        }
    }
}

extern "C" void kernel_launch(void* const* d_in, const int* in_sizes, int n_in,
                              void* d_out, int out_size) {
    const float* x     = (const float*)d_in[0];
    const float* W_in  = (const float*)d_in[1];
    const float* b_in  = (const float*)d_in[2];
    const float* W_out = (const float*)d_in[3];
    const float* b_out = (const float*)d_in[4];
    const float* wf    = (const float*)d_in[5];
    const float* wi    = (const float*)d_in[6];
    const float* wg    = (const float*)d_in[7];
    const float* wo    = (const float*)d_in[8];
    float* out = (float*)d_out;

    qlstm_kernel<<<HALF, 32>>>(x, W_in, b_in, W_out, b_out, wf, wi, wg, wo, out);
}

// round 14
// speedup vs baseline: 1.6580x; 1.1040x over previous
#include <cuda_runtime.h>
#include <cstdint>

// QuantumLSTM: B=2048, T=64, IN=8, HID=6 qubits, OUT=8, NLAYERS=2.
//
// X-basis pure-phase formulation:
//   beta^{(g)}_k = a_{sigma^2(k)} + C^{(g)}_k,
//   <Z_w> = (1/64) sum_k cos(beta_{k xor e_w} - beta_k)  (pair-dedup, weight 2).
// R14 = R9 (best, 57.2us) + depth-halved reduce (radix-4 gate stage and
// radix-4 w-stage; 5 dependent shuffle stages -> 3) + x(t+1) prefetch.
// One warp per sample, 2048 warps.

namespace {
constexpr int BATCH = 2048;
constexpr int TSTEPS = 64;
constexpr float TWO_PI = 6.28318530717958647692f;
}

__device__ __forceinline__ float shx(float v, int m) {
    return __shfl_xor_sync(0xffffffffu, v, m);
}
__device__ __forceinline__ float shi(float v, int src) {
    return __shfl_sync(0xffffffffu, v, src);
}
__device__ __forceinline__ float tanh_fast(float x) {
    float r;
    asm("tanh.approx.f32 %0, %1;" : "=f"(r) : "f"(x));
    return r;
}
__device__ __forceinline__ float reduce2pi(float a) {
    return a - TWO_PI * rintf(a * (1.0f / TWO_PI));
}

// X-basis CNOT ring composed permutation: state'[k] = state[sigma(k)].
__device__ __forceinline__ int ring_src_x(int k) {
    int j = k;
    j ^= (j >> 5) & 1;
    j ^= (j & 1) << 1;
    j ^= ((j >> 1) & 1) << 2;
    j ^= ((j >> 2) & 1) << 3;
    j ^= ((j >> 3) & 1) << 4;
    j ^= ((j >> 4) & 1) << 5;
    return j;
}

__device__ __forceinline__ float phaseA(const float* w6, int j) {
    float s = 0.0f;
#pragma unroll
    for (int w = 0; w < 6; w++)
        s += (((j >> (5 - w)) & 1) ? 0.5f : -0.5f) * w6[w];
    return s;
}

// C^{(g)}(j) = A1(sigma^2 j) + A2(sigma j)
__device__ __forceinline__ float Cphase(const float* wp, int j) {
    int s1 = ring_src_x(j);
    return phaseA(wp, ring_src_x(s1)) + phaseA(wp + 6, s1);
}

__global__ void __launch_bounds__(32, 14) qlstm_kernel(
    const float* __restrict__ x,      // [B, T, 8]
    const float* __restrict__ W_in,   // [6, 16]
    const float* __restrict__ b_in,   // [6]
    const float* __restrict__ W_out,  // [8, 6]
    const float* __restrict__ b_out,  // [8]
    const float* __restrict__ wf,     // [2, 6]
    const float* __restrict__ wi,
    const float* __restrict__ wg,
    const float* __restrict__ wo,
    float* __restrict__ out)          // [B, T, 8]
{
    const int lane = threadIdx.x;
    const int s = blockIdx.x;

    const int kLo = lane;
    const int kHi = lane + 32;
    const int lg = (lane >> 3) & 3;   // lane's gate-group bits
    const int ch = lane & 7;          // lane's LSTM channel

    // ---- embedding sign vectors for aperm = a(sigma^2(k)) ----
    const int s2Lo = ring_src_x(ring_src_x(kLo));
    const int s2Hi = ring_src_x(ring_src_x(kHi));
    float sgnP[6], sgnH[6];
#pragma unroll
    for (int w = 0; w < 6; w++) {
        sgnP[w] = ((s2Lo >> (5 - w)) & 1) ? 0.5f : -0.5f;
        sgnH[w] = ((s2Hi >> (5 - w)) & 1) ? 0.5f : -0.5f;
    }

    // ---- fold sign vectors through W_in: apl = WP.[h;x] + bP ----
    float WP[16], WH[16];
    float bP = 0.0f, bH = 0.0f;
#pragma unroll
    for (int j = 0; j < 16; j++) { WP[j] = 0.0f; WH[j] = 0.0f; }
#pragma unroll
    for (int w = 0; w < 6; w++) {
        float bw = b_in[w];
        bP = fmaf(sgnP[w], bw, bP);
        bH = fmaf(sgnH[w], bw, bH);
#pragma unroll
        for (int j = 0; j < 16; j++) {
            float wv = W_in[w * 16 + j];
            WP[j] = fmaf(sgnP[w], wv, WP[j]);
            WH[j] = fmaf(sgnH[w], wv, WH[j]);
        }
    }

    // ---- per-gate constants, PRE-PERMUTED by lane's gate bits:
    // slot jg holds constants for gate g = jg ^ lg.
    float dc0P[4], dcSP[4][5];
#pragma unroll
    for (int jg = 0; jg < 4; jg++) {
        int g = jg ^ lg;
        const float* wp = (g == 0) ? wf : (g == 1) ? wi : (g == 2) ? wg : wo;
        float cLo = Cphase(wp, kLo);
        float cHi = Cphase(wp, kHi);
        dc0P[jg] = reduce2pi(cHi - cLo);
#pragma unroll
        for (int i = 0; i < 5; i++) {
            int m = 16 >> i;
            int kSel = (lane & m) ? kHi : kLo;
            float cS = (lane & m) ? cHi : cLo;
            dcSP[jg][i] = reduce2pi(Cphase(wp, kSel ^ m) - cS);
        }
    }

    // ---- W_out row: weight 2 per wire (pair-dedup) ----
    float woutS[6];
#pragma unroll
    for (int w = 0; w < 6; w++)
        woutS[w] = W_out[ch * 6 + w] * (2.0f / 64.0f);
    const float boutv = b_out[ch];

    // ---- branch-free activation: act = aT * tanh(sT*z) + bT ----
    const float sT = (lg == 2) ? 1.0f : 0.5f;
    const float aT = (lg == 2) ? 1.0f : 0.5f;
    const float bT = (lg == 2) ? 0.0f : 0.5f;

    // w-stage routing bits
    const bool b0 = (lane & 1) != 0;
    const bool b1 = (lane & 2) != 0;
    const bool b2 = (lane & 4) != 0;

    const float4* xrow = (const float4*)(x + (size_t)s * TSTEPS * 8);
    float* orow = out + (size_t)s * TSTEPS * 8;

    float creg = 0.0f, hreg = 0.0f;  // lane owns channel ch (x4 replicated)

    // software-pipelined x loads
    float4 xa = xrow[0];
    float4 xb = xrow[1];

    for (int t = 0; t < TSTEPS; t++) {
        float4 xaCur = xa, xbCur = xb;
        if (t + 1 < TSTEPS) {
            xa = xrow[(t + 1) * 2];
            xb = xrow[(t + 1) * 2 + 1];
        }

        // ---- x-chain (independent of h) ----
        float xpl = bP, xph = bH;
        {
            float xs[8] = {xaCur.x, xaCur.y, xaCur.z, xaCur.w,
                           xbCur.x, xbCur.y, xbCur.z, xbCur.w};
#pragma unroll
            for (int j = 0; j < 8; j++) {
                xpl = fmaf(WP[8 + j], xs[j], xpl);
                xph = fmaf(WH[8 + j], xs[j], xph);
            }
        }

        // ---- h-chain (recurrence-critical), joined with x-chain ----
        float hpl = 0.0f, hph = 0.0f;
#pragma unroll
        for (int j = 0; j < 8; j++) {
            float hj = shi(hreg, j);
            hpl = fmaf(WP[j], hj, hpl);
            hph = fmaf(WH[j], hj, hph);
        }
        float apl = reduce2pi(xpl + hpl);
        float aph = reduce2pi(xph + hph);

        // ---- one shuffle per wire serves both pair orientations ----
        float Da0 = aph - apl;
        float DaS[5];
#pragma unroll
        for (int i = 0; i < 5; i++) {
            const int m = 16 >> i;
            const bool b = (lane & m) != 0;
            float send = b ? apl : aph;   // partner needs my OPPOSITE slot
            float own  = b ? aph : apl;
            DaS[i] = shx(send, m) - own;
        }

        // ---- per-lane partials, dense gate-permuted slots: q[jg*6 + w] ----
        float q[24];
#pragma unroll
        for (int jg = 0; jg < 4; jg++) {
            q[jg * 6] = __cosf(Da0 + dc0P[jg]);
#pragma unroll
            for (int i = 0; i < 5; i++)
                q[jg * 6 + 1 + i] = __cosf(DaS[i] + dcSP[jg][i]);
        }

        // ---- gate stage: RADIX-4, selection-free, depth 1 ----
        // masks 8,16,24 simultaneously; slot jg in partner lane holds gate lg.
#pragma unroll
        for (int i = 0; i < 6; i++) {
            float a8  = shx(q[i + 6], 8);
            float a16 = shx(q[i + 12], 16);
            float a24 = shx(q[i + 18], 24);
            q[i] += a8 + a16 + a24;
        }

        // ---- w-stage: RADIX-4 over masks {4,2}, then mask-1 fold ----
        // slots 0..5 hold T_w; pads 6,7 = 0. Target w = b0 + 2*b1 + 4*b2.
        float r0, r1;
        {
            const float z6 = 0.0f, z7 = 0.0f;
#pragma unroll
            for (int i = 0; i < 2; i++) {
                float v0 = q[i];
                float v2 = q[i + 2];
                float v4 = q[i + 4];
                float v6 = (i == 0) ? z6 : z7;
                // candidates indexed by (b2, b1): v0=(0,0) v2=(0,1) v4=(1,0) v6=(1,1)
                float c00 = b2 ? v4 : v0;   // b1 = 0 candidate (own b2)
                float c01 = b2 ? v6 : v2;   // b1 = 1 candidate (own b2)
                float d00 = b2 ? v0 : v4;   // b2 flipped, b1 = 0
                float d01 = b2 ? v2 : v6;   // b2 flipped, b1 = 1
                float own = b1 ? c01 : c00;
                float sm2 = b1 ? c00 : c01;   // b1 flipped
                float sm4 = b1 ? d01 : d00;   // b2 flipped
                float sm6 = b1 ? d00 : d01;   // both flipped
                float res = own + shx(sm2, 2) + shx(sm4, 4) + shx(sm6, 6);
                if (i == 0) r0 = res; else r1 = res;
            }
        }
        float keep1 = b0 ? r1 : r0;
        float send1 = b0 ? r0 : r1;
        float S = keep1 + shx(send1, 1);
        // lane l holds S = e[gate = l>>3][w = l&7]; w=6,7 are zero pads.

        // ---- z for (gate = l>>3, ch = l&7) via shuffle-matmul ----
        const int base = lane & 24;
        float z = boutv;
#pragma unroll
        for (int w = 0; w < 6; w++) z = fmaf(woutS[w], shi(S, base + w), z);

        // ---- activation FIRST (one MUFU.TANH per lane), then gather ----
        float act = fmaf(aT, tanh_fast(sT * z), bT);
        float fg = shi(act, ch);
        float ig = shi(act, ch + 8);
        float gg = shi(act, ch + 16);
        float og = shi(act, ch + 24);

        // ---- LSTM cell ----
        creg = fmaf(fg, creg, ig * gg);
        hreg = og * tanh_fast(creg);
        if (lane < 8) orow[t * 8 + lane] = hreg;
    }
}

extern "C" void kernel_launch(void* const* d_in, const int* in_sizes, int n_in,
                              void* d_out, int out_size) {
    const float* x     = (const float*)d_in[0];
    const float* W_in  = (const float*)d_in[1];
    const float* b_in  = (const float*)d_in[2];
    const float* W_out = (const float*)d_in[3];
    const float* b_out = (const float*)d_in[4];
    const float* wf    = (const float*)d_in[5];
    const float* wi    = (const float*)d_in[6];
    const float* wg    = (const float*)d_in[7];
    const float* wo    = (const float*)d_in[8];
    float* out = (float*)d_out;

    qlstm_kernel<<<BATCH, 32>>>(x, W_in, b_in, W_out, b_out, wf, wi, wg, wo, out);
}

// round 17
// speedup vs baseline: 1.7490x; 1.0549x over previous
#include <cuda_runtime.h>
#include <cstdint>

// QuantumLSTM: B=2048, T=64, IN=8, HID=6 qubits, OUT=8, NLAYERS=2.
//
// X-basis pure-phase formulation:
//   beta^{(g)}_k = a_{sigma^2(k)} + C^{(g)}_k,
//   <Z_w> = (1/64) sum_k cos(beta_{k xor e_w} - beta_k)  (pair-dedup, weight 2).
// FACTORED COSINES: cos(Da+dc) expanded against per-lane constant
// (cos dc, -sin dc) pairs; only 6 sincos per step instead of 24 cos.
// MUFU ops/step 26 -> 14. One warp per sample, 2048 warps.

namespace {
constexpr int BATCH = 2048;
constexpr int TSTEPS = 64;
constexpr float TWO_PI = 6.28318530717958647692f;
}

__device__ __forceinline__ float shx(float v, int m) {
    return __shfl_xor_sync(0xffffffffu, v, m);
}
__device__ __forceinline__ float shi(float v, int src) {
    return __shfl_sync(0xffffffffu, v, src);
}
__device__ __forceinline__ float tanh_fast(float x) {
    float r;
    asm("tanh.approx.f32 %0, %1;" : "=f"(r) : "f"(x));
    return r;
}
__device__ __forceinline__ float reduce2pi(float a) {
    return a - TWO_PI * rintf(a * (1.0f / TWO_PI));
}

// X-basis CNOT ring composed permutation: state'[k] = state[sigma(k)].
__device__ __forceinline__ int ring_src_x(int k) {
    int j = k;
    j ^= (j >> 5) & 1;
    j ^= (j & 1) << 1;
    j ^= ((j >> 1) & 1) << 2;
    j ^= ((j >> 2) & 1) << 3;
    j ^= ((j >> 3) & 1) << 4;
    j ^= ((j >> 4) & 1) << 5;
    return j;
}

__device__ __forceinline__ float phaseA(const float* w6, int j) {
    float s = 0.0f;
#pragma unroll
    for (int w = 0; w < 6; w++)
        s += (((j >> (5 - w)) & 1) ? 0.5f : -0.5f) * w6[w];
    return s;
}

// C^{(g)}(j) = A1(sigma^2 j) + A2(sigma j)
__device__ __forceinline__ float Cphase(const float* wp, int j) {
    int s1 = ring_src_x(j);
    return phaseA(wp, ring_src_x(s1)) + phaseA(wp + 6, s1);
}

__global__ void __launch_bounds__(32, 14) qlstm_kernel(
    const float* __restrict__ x,      // [B, T, 8]
    const float* __restrict__ W_in,   // [6, 16]
    const float* __restrict__ b_in,   // [6]
    const float* __restrict__ W_out,  // [8, 6]
    const float* __restrict__ b_out,  // [8]
    const float* __restrict__ wf,     // [2, 6]
    const float* __restrict__ wi,
    const float* __restrict__ wg,
    const float* __restrict__ wo,
    float* __restrict__ out)          // [B, T, 8]
{
    const int lane = threadIdx.x;
    const int s = blockIdx.x;

    const int kLo = lane;
    const int kHi = lane + 32;
    const int lg = (lane >> 3) & 3;   // lane's gate-group bits
    const int ch = lane & 7;          // lane's LSTM channel

    // ---- embedding sign vectors for aperm = a(sigma^2(k)) ----
    const int s2Lo = ring_src_x(ring_src_x(kLo));
    const int s2Hi = ring_src_x(ring_src_x(kHi));
    float sgnP[6], sgnH[6];
#pragma unroll
    for (int w = 0; w < 6; w++) {
        sgnP[w] = ((s2Lo >> (5 - w)) & 1) ? 0.5f : -0.5f;
        sgnH[w] = ((s2Hi >> (5 - w)) & 1) ? 0.5f : -0.5f;
    }

    // ---- fold sign vectors through W_in: apl = WP.[h;x] + bP ----
    float WP[16], WH[16];
    float bP = 0.0f, bH = 0.0f;
#pragma unroll
    for (int j = 0; j < 16; j++) { WP[j] = 0.0f; WH[j] = 0.0f; }
#pragma unroll
    for (int w = 0; w < 6; w++) {
        float bw = b_in[w];
        bP = fmaf(sgnP[w], bw, bP);
        bH = fmaf(sgnH[w], bw, bH);
#pragma unroll
        for (int j = 0; j < 16; j++) {
            float wv = W_in[w * 16 + j];
            WP[j] = fmaf(sgnP[w], wv, WP[j]);
            WH[j] = fmaf(sgnH[w], wv, WH[j]);
        }
    }

    // ---- per-gate constant phase diffs -> (cos, -sin) pairs,
    //      PRE-PERMUTED by lane's gate bits: slot jg = gate jg ^ lg ----
    float cdc0[4], nsdc0[4], cdcS[4][5], nsdcS[4][5];
#pragma unroll
    for (int jg = 0; jg < 4; jg++) {
        int g = jg ^ lg;
        const float* wp = (g == 0) ? wf : (g == 1) ? wi : (g == 2) ? wg : wo;
        float cLo = Cphase(wp, kLo);
        float cHi = Cphase(wp, kHi);
        float sd, cd;
        __sincosf(reduce2pi(cHi - cLo), &sd, &cd);
        cdc0[jg] = cd;
        nsdc0[jg] = -sd;
#pragma unroll
        for (int i = 0; i < 5; i++) {
            int m = 16 >> i;
            int kSel = (lane & m) ? kHi : kLo;
            float cS = (lane & m) ? cHi : cLo;
            __sincosf(reduce2pi(Cphase(wp, kSel ^ m) - cS), &sd, &cd);
            cdcS[jg][i] = cd;
            nsdcS[jg][i] = -sd;
        }
    }

    // ---- W_out row: weight 2 per wire (pair-dedup) ----
    float woutS[6];
#pragma unroll
    for (int w = 0; w < 6; w++)
        woutS[w] = W_out[ch * 6 + w] * (2.0f / 64.0f);
    const float boutv = b_out[ch];

    // ---- branch-free activation: act = aT * tanh(sT*z) + bT ----
    const float sT = (lg == 2) ? 1.0f : 0.5f;
    const float aT = (lg == 2) ? 1.0f : 0.5f;
    const float bT = (lg == 2) ? 0.0f : 0.5f;

    const float4* xrow = (const float4*)(x + (size_t)s * TSTEPS * 8);
    float* orow = out + (size_t)s * TSTEPS * 8;

    float creg = 0.0f, hreg = 0.0f;  // lane owns channel ch (x4 replicated)

    // software-pipelined x loads
    float4 xa = xrow[0];
    float4 xb = xrow[1];

    for (int t = 0; t < TSTEPS; t++) {
        float4 xaCur = xa, xbCur = xb;
        if (t + 1 < TSTEPS) {
            xa = xrow[(t + 1) * 2];
            xb = xrow[(t + 1) * 2 + 1];
        }

        // ---- x-chain (independent of h) ----
        float xpl = bP, xph = bH;
        {
            float xs[8] = {xaCur.x, xaCur.y, xaCur.z, xaCur.w,
                           xbCur.x, xbCur.y, xbCur.z, xbCur.w};
#pragma unroll
            for (int j = 0; j < 8; j++) {
                xpl = fmaf(WP[8 + j], xs[j], xpl);
                xph = fmaf(WH[8 + j], xs[j], xph);
            }
        }

        // ---- h-chain (recurrence-critical), joined with x-chain ----
        float hpl = 0.0f, hph = 0.0f;
#pragma unroll
        for (int j = 0; j < 8; j++) {
            float hj = shi(hreg, j);
            hpl = fmaf(WP[j], hj, hpl);
            hph = fmaf(WH[j], hj, hph);
        }
        float apl = reduce2pi(xpl + hpl);
        float aph = reduce2pi(xph + hph);

        // ---- partials via factored cosines: q[jg*6 + w] ----
        float q[24];
        {
            // wire 0 (slot pair, no shuffle)
            float s0, c0;
            __sincosf(aph - apl, &s0, &c0);
#pragma unroll
            for (int jg = 0; jg < 4; jg++)
                q[jg * 6] = fmaf(c0, cdc0[jg], s0 * nsdc0[jg]);
        }
#pragma unroll
        for (int i = 0; i < 5; i++) {
            const int m = 16 >> i;
            const bool b = (lane & m) != 0;
            float send = b ? apl : aph;   // partner needs my OPPOSITE slot
            float own  = b ? aph : apl;
            float Da = shx(send, m) - own;
            float sS, cS;
            __sincosf(Da, &sS, &cS);
#pragma unroll
            for (int jg = 0; jg < 4; jg++)
                q[jg * 6 + 1 + i] = fmaf(cS, cdcS[jg][i], sS * nsdcS[jg][i]);
        }

        // ---- gate stages: SELECTION-FREE (xor-permuted), dense layout ----
#pragma unroll
        for (int i = 0; i < 12; i++)
            q[i] += shx(q[i + 12], 16);
#pragma unroll
        for (int i = 0; i < 6; i++)
            q[i] += shx(q[i + 6], 8);

        // ---- w-stages (routed): masks 4, 2, 1 over 8 slots (2 zero pads) ----
        float qq[8] = {q[0], q[1], q[2], q[3], q[4], q[5], 0.0f, 0.0f};
#pragma unroll
        for (int half = 4; half >= 1; half >>= 1) {
            const bool up = (lane & half) != 0;
#pragma unroll
            for (int i = 0; i < half; i++) {
                float keep = up ? qq[i + half] : qq[i];
                float send = up ? qq[i] : qq[i + half];
                qq[i] = keep + shx(send, half);
            }
        }
        // lane l holds S for (gate = l>>3, w = l&7); w=6,7 are zero pads.
        const float S = qq[0];

        // ---- z for (gate = l>>3, ch = l&7) via shuffle-matmul ----
        const int base = lane & 24;
        float z = boutv;
#pragma unroll
        for (int w = 0; w < 6; w++) z = fmaf(woutS[w], shi(S, base + w), z);

        // ---- activation FIRST (one MUFU.TANH per lane), then gather ----
        float act = fmaf(aT, tanh_fast(sT * z), bT);
        float fg = shi(act, ch);
        float ig = shi(act, ch + 8);
        float gg = shi(act, ch + 16);
        float og = shi(act, ch + 24);

        // ---- LSTM cell ----
        creg = fmaf(fg, creg, ig * gg);
        hreg = og * tanh_fast(creg);
        if (lane < 8) orow[t * 8 + lane] = hreg;
    }
}

extern "C" void kernel_launch(void* const* d_in, const int* in_sizes, int n_in,
                              void* d_out, int out_size) {
    const float* x     = (const float*)d_in[0];
    const float* W_in  = (const float*)d_in[1];
    const float* b_in  = (const float*)d_in[2];
    const float* W_out = (const float*)d_in[3];
    const float* b_out = (const float*)d_in[4];
    const float* wf    = (const float*)d_in[5];
    const float* wi    = (const float*)d_in[6];
    const float* wg    = (const float*)d_in[7];
    const float* wo    = (const float*)d_in[8];
    float* out = (float*)d_out;

    qlstm_kernel<<<BATCH, 32>>>(x, W_in, b_in, W_out, b_out, wf, wi, wg, wo, out);
}